// round 13
// baseline (speedup 1.0000x reference)
#include <cuda_runtime.h>
#include <cuda_bf16.h>
#include <math.h>
#include <stdint.h>

// ---------------------------------------------------------------------------
// Problem constants
// ---------------------------------------------------------------------------
#define BB    1024
#define SS    32
#define DD    512
#define NDICT 16384
#define TOPK  32
#define NSEL  44
#define NBINS 4096        // 12-bit histogram over abs bf16 bits (key >> 3)
#define CANDMAX 512

// ---------------------------------------------------------------------------
// Scratch
// ---------------------------------------------------------------------------
constexpr size_t NX     = 2ULL * BB * DD;          // 2048x512
constexpr size_t OFF_X  = 0;
constexpr size_t OFF_H  = OFF_X + NX;
constexpr size_t OFF_P  = OFF_H + NX;
constexpr size_t OFF_W  = OFF_P + NX;              // combined fp32 W: 2 x 16384 x 512
constexpr size_t NW     = 2ULL * NDICT * DD;
constexpr size_t OFF_REP= OFF_W + NW;              // rep: 2 x 2048 x 512
constexpr size_t NREP   = 2ULL * 2 * BB * DD;
constexpr size_t TOTAL  = OFF_REP + NREP;

__device__ float g_scr[TOTAL];

__device__ __nv_bfloat16 g_A[2048ULL * DD];              // pooled p, bf16
__device__ __nv_bfloat16 g_B[2ULL * NDICT * DD];         // combined W, bf16
__device__ __nv_bfloat16 g_C[2ULL * 2 * BB * NDICT];     // approx coeffs, bf16

// Output layout (floats)
constexpr size_t OUT_CC = 0;
constexpr size_t OUT_RC = 16384;
constexpr size_t OUT_CN = 22528;
constexpr size_t OUT_RN = 38912;
constexpr size_t OUT_SP = 45056;

// ---------------------------------------------------------------------------
// Portable PTX helpers
// ---------------------------------------------------------------------------
__device__ __forceinline__ uint32_t smem_u32(const void* p) {
    uint32_t a;
    asm("{ .reg .u64 t; cvta.to.shared.u64 t, %1; cvt.u32.u64 %0, t; }" : "=r"(a) : "l"(p));
    return a;
}
#define CP_ASYNC16(dst, src) \
    asm volatile("cp.async.cg.shared.global [%0], [%1], 16;" :: "r"(dst), "l"(src))
#define CP_COMMIT()  asm volatile("cp.async.commit_group;" ::: "memory")
#define CP_WAIT_1()  asm volatile("cp.async.wait_group 1;" ::: "memory")
#define CP_WAIT_0()  asm volatile("cp.async.wait_group 0;" ::: "memory")

#define LDMATRIX_X4(r0, r1, r2, r3, addr) \
    asm volatile("ldmatrix.sync.aligned.m8n8.x4.shared.b16 {%0,%1,%2,%3}, [%4];" \
                 : "=r"(r0), "=r"(r1), "=r"(r2), "=r"(r3) : "r"(addr))

#define MMA_BF16(c0, c1, c2, c3, a0, a1, a2, a3, b0, b1) \
    asm volatile("mma.sync.aligned.m16n8k16.row.col.f32.bf16.bf16.f32 " \
                 "{%0,%1,%2,%3}, {%4,%5,%6,%7}, {%8,%9}, {%0,%1,%2,%3};" \
                 : "+f"(c0), "+f"(c1), "+f"(c2), "+f"(c3) \
                 : "r"(a0), "r"(a1), "r"(a2), "r"(a3), "r"(b0), "r"(b1))

#define SWZ128(off) ((off) ^ (((off) >> 3) & 0x70))

__device__ __forceinline__ float silu(float v) { return v / (1.0f + expf(-v)); }

// ---------------------------------------------------------------------------
// 1) Combine router weights -> fp32 W + bf16 B'
// ---------------------------------------------------------------------------
__global__ __launch_bounds__(256) void combine_kernel(const float4* __restrict__ router,
                                                      const float4* __restrict__ cdelta,
                                                      const float4* __restrict__ rdelta)
{
    size_t i = (size_t)blockIdx.x * 256 + threadIdx.x;
    float4 r = router[i];
    float4 c = cdelta[i];
    float4 d = rdelta[i];
    float4 w0 = make_float4(r.x + 0.3f * c.x, r.y + 0.3f * c.y,
                            r.z + 0.3f * c.z, r.w + 0.3f * c.w);
    float4 w1 = make_float4(r.x + 0.3f * d.x, r.y + 0.3f * d.y,
                            r.z + 0.3f * d.z, r.w + 0.3f * d.w);
    ((float4*)&g_scr[OFF_W])[i] = w0;
    ((float4*)&g_scr[OFF_W + (size_t)NDICT * DD])[i] = w1;
    __nv_bfloat162 p0 = __floats2bfloat162_rn(w0.x, w0.y);
    __nv_bfloat162 p1 = __floats2bfloat162_rn(w0.z, w0.w);
    __nv_bfloat162 q0 = __floats2bfloat162_rn(w1.x, w1.y);
    __nv_bfloat162 q1 = __floats2bfloat162_rn(w1.z, w1.w);
    uint2 pk0; pk0.x = *(uint32_t*)&p0; pk0.y = *(uint32_t*)&p1;
    uint2 pk1; pk1.x = *(uint32_t*)&q0; pk1.y = *(uint32_t*)&q1;
    *(uint2*)(g_B + i * 4) = pk0;
    *(uint2*)(g_B + (size_t)NDICT * DD + i * 4) = pk1;
}

// ---------------------------------------------------------------------------
// 2) Pool
// ---------------------------------------------------------------------------
__global__ __launch_bounds__(128) void pool_kernel(const int* __restrict__ clean,
                                                   const int* __restrict__ noisy,
                                                   const float* __restrict__ emb)
{
    int b = blockIdx.x, w = blockIdx.y;
    const int* toks = (w ? noisy : clean) + b * SS;
    __shared__ int st[SS];
    if (threadIdx.x < SS) st[threadIdx.x] = toks[threadIdx.x];
    __syncthreads();
    int c = threadIdx.x;
    float4 acc = make_float4(0.f, 0.f, 0.f, 0.f);
    #pragma unroll
    for (int s = 0; s < SS; s++) {
        const float4 v = *(const float4*)(emb + (size_t)st[s] * DD + c * 4);
        acc.x += v.x; acc.y += v.y; acc.z += v.z; acc.w += v.w;
    }
    const float inv = 1.0f / 32.0f;
    *(float4*)(&g_scr[OFF_X + ((size_t)(w * BB + b)) * DD + c * 4]) =
        make_float4(acc.x * inv, acc.y * inv, acc.z * inv, acc.w * inv);
}

// ---------------------------------------------------------------------------
// 3) MLP GEMM: 64x64 tile, 128 threads, 8x4 microtile (1.5 B LDS per FMA),
//    BK=16, fused bias/act/bf16 epilogue. Per-element fp32 k-order unchanged.
// ---------------------------------------------------------------------------
__global__ __launch_bounds__(128) void mlp_gemm(const float* __restrict__ A,
                                                const float* __restrict__ Bw,
                                                const float* __restrict__ bias,
                                                float* __restrict__ C,
                                                __nv_bfloat16* __restrict__ Cbf,
                                                int act)
{
    constexpr int BM = 64, BN = 64, BK = 16;
    const int K = DD, N = DD;
    __shared__ float As[BK][BM];
    __shared__ float Bs[BK][BN];
    int tid = threadIdx.x;
    int tx = tid & 15, ty = tid >> 4;         // tx 0..15 (4 cols), ty 0..7 (8 rows)
    int row0 = blockIdx.y * BM, col0 = blockIdx.x * BN;
    float acc[8][4] = {};

    // loads: A rows lr, lr+32; B rows lr, lr+32; cols lc..lc+3
    int lr = tid >> 2;                        // 0..31
    int lc = (tid & 3) * 4;                   // 0,4,8,12
    const float* Ag0 = A  + (size_t)(row0 + lr) * K + lc;
    const float* Ag1 = Ag0 + (size_t)32 * K;
    const float* Bg0 = Bw + (size_t)(col0 + lr) * K + lc;
    const float* Bg1 = Bg0 + (size_t)32 * K;

    float4 a0n = *(const float4*)Ag0;
    float4 a1n = *(const float4*)Ag1;
    float4 b0n = *(const float4*)Bg0;
    float4 b1n = *(const float4*)Bg1;

    for (int k0 = 0; k0 < K; k0 += BK) {
        As[lc + 0][lr]      = a0n.x; As[lc + 1][lr]      = a0n.y;
        As[lc + 2][lr]      = a0n.z; As[lc + 3][lr]      = a0n.w;
        As[lc + 0][lr + 32] = a1n.x; As[lc + 1][lr + 32] = a1n.y;
        As[lc + 2][lr + 32] = a1n.z; As[lc + 3][lr + 32] = a1n.w;
        Bs[lc + 0][lr]      = b0n.x; Bs[lc + 1][lr]      = b0n.y;
        Bs[lc + 2][lr]      = b0n.z; Bs[lc + 3][lr]      = b0n.w;
        Bs[lc + 0][lr + 32] = b1n.x; Bs[lc + 1][lr + 32] = b1n.y;
        Bs[lc + 2][lr + 32] = b1n.z; Bs[lc + 3][lr + 32] = b1n.w;
        __syncthreads();
        if (k0 + BK < K) {
            a0n = *(const float4*)(Ag0 + k0 + BK);
            a1n = *(const float4*)(Ag1 + k0 + BK);
            b0n = *(const float4*)(Bg0 + k0 + BK);
            b1n = *(const float4*)(Bg1 + k0 + BK);
        }
        #pragma unroll
        for (int k = 0; k < BK; k++) {
            float4 aA = *(const float4*)&As[k][ty * 8];
            float4 aB = *(const float4*)&As[k][ty * 8 + 4];
            float4 b4 = *(const float4*)&Bs[k][tx * 4];
            float ar[8] = {aA.x, aA.y, aA.z, aA.w, aB.x, aB.y, aB.z, aB.w};
            float br[4] = {b4.x, b4.y, b4.z, b4.w};
            #pragma unroll
            for (int i = 0; i < 8; i++)
                #pragma unroll
                for (int j = 0; j < 4; j++)
                    acc[i][j] += ar[i] * br[j];
        }
        __syncthreads();
    }

    float4 bv = *(const float4*)(bias + col0 + tx * 4);
    #pragma unroll
    for (int i = 0; i < 8; i++) {
        int r = row0 + ty * 8 + i;
        float4 v = make_float4(acc[i][0] + bv.x, acc[i][1] + bv.y,
                               acc[i][2] + bv.z, acc[i][3] + bv.w);
        if (act) { v.x = silu(v.x); v.y = silu(v.y); v.z = silu(v.z); v.w = silu(v.w); }
        *(float4*)(C + (size_t)r * N + col0 + tx * 4) = v;
        if (Cbf) {
            __nv_bfloat162 q0 = __floats2bfloat162_rn(v.x, v.y);
            __nv_bfloat162 q1 = __floats2bfloat162_rn(v.z, v.w);
            uint2 pk; pk.x = *(uint32_t*)&q0; pk.y = *(uint32_t*)&q1;
            *(uint2*)(Cbf + (size_t)r * N + col0 + tx * 4) = pk;
        }
    }
}

// ---------------------------------------------------------------------------
// 4) bf16 mma.sync GEMM (R8/R11 version — at tensor-issue ceiling)
// ---------------------------------------------------------------------------
constexpr int      NKB      = DD / 64;
constexpr uint32_t TILE_A   = 128 * 128;
constexpr uint32_t TILE_B   = 128 * 128;
constexpr uint32_t STAGE_SZ = TILE_A + TILE_B;
constexpr uint32_t EPI_LD   = 132;
constexpr uint32_t MM_SMEM  = 1024 + 3 * STAGE_SZ;

__device__ __forceinline__ void mm_load(uint32_t sb, const char* Ag, const char* Bg,
                                        int kb, int s, int tid)
{
    uint32_t base = sb + s * STAGE_SZ;
    #pragma unroll
    for (int i = 0; i < 4; i++) {
        int idx = tid + i * 256;
        int r = idx >> 3, c = idx & 7;
        uint32_t off = (uint32_t)(r * 128 + c * 16);
        CP_ASYNC16(base + SWZ128(off), Ag + (size_t)r * 1024 + kb * 128 + c * 16);
    }
    #pragma unroll
    for (int i = 0; i < 4; i++) {
        int idx = tid + i * 256;
        int r = idx >> 3, c = idx & 7;
        uint32_t off = (uint32_t)(r * 128 + c * 16);
        CP_ASYNC16(base + TILE_A + SWZ128(off), Bg + (size_t)r * 1024 + kb * 128 + c * 16);
    }
    CP_COMMIT();
}

__global__ void __launch_bounds__(256, 2) mma_gemm_kernel()
{
    extern __shared__ char smem_raw[];
    uint32_t sb0 = smem_u32(smem_raw);
    uint32_t sb  = (sb0 + 1023u) & ~1023u;
    char* smem = smem_raw + (sb - sb0);

    int tid = threadIdx.x, wid = tid >> 5, lane = tid & 31;
    int nt = blockIdx.x, mt = blockIdx.y, e = blockIdx.z;
    int wm = wid & 1, wn = wid >> 1;

    const char* Ag = (const char*)g_A + (size_t)(mt * 128) * 1024;
    const char* Bg = (const char*)g_B + ((size_t)(e * NDICT + nt * 128)) * 1024;

    float acc[4][4][4];
    #pragma unroll
    for (int i = 0; i < 4; i++)
        #pragma unroll
        for (int j = 0; j < 4; j++)
            #pragma unroll
            for (int v = 0; v < 4; v++) acc[i][j][v] = 0.f;

    uint32_t aOff[4], bOff[2];
    #pragma unroll
    for (int mf = 0; mf < 4; mf++)
        aOff[mf] = (uint32_t)((wm * 64 + mf * 16 + (lane & 15)) * 128 + ((lane >> 4) << 4));
    #pragma unroll
    for (int nf2 = 0; nf2 < 2; nf2++)
        bOff[nf2] = (uint32_t)((wn * 32 + nf2 * 16 + (lane & 7) + ((lane >> 4) << 3)) * 128
                               + (((lane >> 3) & 1) << 4));

    mm_load(sb, Ag, Bg, 0, 0, tid);
    mm_load(sb, Ag, Bg, 1, 1, tid);

    for (int kb = 0; kb < NKB; kb++) {
        int s = kb % 3;
        if (kb + 1 < NKB) { CP_WAIT_1(); } else { CP_WAIT_0(); }
        __syncthreads();
        if (kb + 2 < NKB) mm_load(sb, Ag, Bg, kb + 2, (kb + 2) % 3, tid);

        uint32_t aBase = sb + s * STAGE_SZ;
        uint32_t bBase = aBase + TILE_A;
        #pragma unroll
        for (int ks = 0; ks < 4; ks++) {
            uint32_t a[4][4], b[2][4];
            #pragma unroll
            for (int mf = 0; mf < 4; mf++) {
                uint32_t ad = aBase + SWZ128(aOff[mf] + ks * 32);
                LDMATRIX_X4(a[mf][0], a[mf][1], a[mf][2], a[mf][3], ad);
            }
            #pragma unroll
            for (int nf2 = 0; nf2 < 2; nf2++) {
                uint32_t bd = bBase + SWZ128(bOff[nf2] + ks * 32);
                LDMATRIX_X4(b[nf2][0], b[nf2][1], b[nf2][2], b[nf2][3], bd);
            }
            #pragma unroll
            for (int mf = 0; mf < 4; mf++)
                #pragma unroll
                for (int nf = 0; nf < 4; nf++) {
                    int n2 = nf >> 1, su = (nf & 1) * 2;
                    MMA_BF16(acc[mf][nf][0], acc[mf][nf][1], acc[mf][nf][2], acc[mf][nf][3],
                             a[mf][0], a[mf][1], a[mf][2], a[mf][3],
                             b[n2][su], b[n2][su + 1]);
                }
        }
    }
    __syncthreads();

    float* epi = (float*)smem;
    #pragma unroll
    for (int mf = 0; mf < 4; mf++) {
        int r0 = wm * 64 + mf * 16 + (lane >> 2);
        #pragma unroll
        for (int nf = 0; nf < 4; nf++) {
            int c0 = wn * 32 + nf * 8 + (lane & 3) * 2;
            *(float2*)&epi[(size_t)r0 * EPI_LD + c0] =
                make_float2(acc[mf][nf][0], acc[mf][nf][1]);
            *(float2*)&epi[(size_t)(r0 + 8) * EPI_LD + c0] =
                make_float2(acc[mf][nf][2], acc[mf][nf][3]);
        }
    }
    __syncthreads();

    __nv_bfloat16* C = g_C + ((size_t)e * 2 * BB + mt * 128) * NDICT + nt * 128;
    #pragma unroll
    for (int it = 0; it < 8; it++) {
        int lin = it * 256 + tid;
        int row = lin >> 4;
        int c0  = (lin & 15) * 8;
        const float* sr = epi + (size_t)row * EPI_LD + c0;
        __nv_bfloat162 p0 = __floats2bfloat162_rn(sr[0], sr[1]);
        __nv_bfloat162 p1 = __floats2bfloat162_rn(sr[2], sr[3]);
        __nv_bfloat162 p2 = __floats2bfloat162_rn(sr[4], sr[5]);
        __nv_bfloat162 p3 = __floats2bfloat162_rn(sr[6], sr[7]);
        uint4 pk;
        pk.x = *(uint32_t*)&p0; pk.y = *(uint32_t*)&p1;
        pk.z = *(uint32_t*)&p2; pk.w = *(uint32_t*)&p3;
        *(uint4*)(C + (size_t)row * NDICT + c0) = pk;
    }
}

// ---------------------------------------------------------------------------
// 5) Top-K: 4096-bin histogram threshold -> exact fp32 recompute -> re-rank
// ---------------------------------------------------------------------------
__global__ __launch_bounds__(256) void topk_kernel(const float* __restrict__ atoms,
                                                   float* __restrict__ out)
{
    int g = blockIdx.x;
    int e = g >> 11;
    int m = g & 2047;
    const uint4* row = (const uint4*)(g_C + ((size_t)e * 2 * BB + m) * NDICT);
    int tid = threadIdx.x;
    int lane = tid & 31, wid = tid >> 5;

    __shared__ int   s_hist[NBINS];     // 16KB
    __shared__ int   s_part[256];
    __shared__ int   s_bstar;
    __shared__ int   s_cnt;
    __shared__ int   s_cand[CANDMAX];
    __shared__ float s_exact[CANDMAX];
    __shared__ int   s_si[TOPK];
    __shared__ float s_sv[TOPK];
    __shared__ float sp[DD];

    for (int i = tid; i < NBINS; i += 256) s_hist[i] = 0;
    if (tid == 0) { s_bstar = -1; s_cnt = 0; }
    sp[tid]       = g_scr[OFF_P + (size_t)m * DD + tid];
    sp[tid + 256] = g_scr[OFF_P + (size_t)m * DD + tid + 256];
    __syncthreads();

    uint4 loc[8];
    #pragma unroll
    for (int it = 0; it < 8; it++) loc[it] = row[it * 256 + tid];

    #pragma unroll
    for (int it = 0; it < 8; it++) {
        uint32_t w4[4] = {loc[it].x, loc[it].y, loc[it].z, loc[it].w};
        #pragma unroll
        for (int w = 0; w < 4; w++) {
            unsigned k0 = (w4[w] & 0xFFFFu) & 0x7FFFu;
            unsigned k1 = (w4[w] >> 16) & 0x7FFFu;
            atomicAdd(&s_hist[k0 >> 3], 1);
            atomicAdd(&s_hist[k1 >> 3], 1);
        }
    }
    __syncthreads();

    int base = tid * 16;
    int psum = 0;
    #pragma unroll
    for (int j = 0; j < 16; j++) psum += s_hist[base + j];
    s_part[tid] = psum;
    __syncthreads();
    for (int off = 1; off < 256; off <<= 1) {
        int v = (tid + off < 256) ? s_part[tid + off] : 0;
        __syncthreads();
        s_part[tid] += v;
        __syncthreads();
    }
    int run = (tid + 1 < 256) ? s_part[tid + 1] : 0;
    int best = -1;
    #pragma unroll
    for (int j = 15; j >= 0; j--) {
        run += s_hist[base + j];
        if (best < 0 && run >= NSEL) best = base + j;
    }
    if (best >= 0) atomicMax(&s_bstar, best);
    __syncthreads();

    unsigned Tkey = (unsigned)s_bstar << 3;

    #pragma unroll
    for (int it = 0; it < 8; it++) {
        uint32_t w4[4] = {loc[it].x, loc[it].y, loc[it].z, loc[it].w};
        int ebase = (it * 256 + tid) * 8;
        #pragma unroll
        for (int w = 0; w < 4; w++) {
            unsigned k0 = (w4[w] & 0xFFFFu) & 0x7FFFu;
            unsigned k1 = (w4[w] >> 16) & 0x7FFFu;
            if (k0 >= Tkey) { int p = atomicAdd(&s_cnt, 1); if (p < CANDMAX) s_cand[p] = ebase + w * 2; }
            if (k1 >= Tkey) { int p = atomicAdd(&s_cnt, 1); if (p < CANDMAX) s_cand[p] = ebase + w * 2 + 1; }
        }
    }
    __syncthreads();
    int M = s_cnt < CANDMAX ? s_cnt : CANDMAX;

    for (int k = wid; k < M; k += 8) {
        const float* wr = &g_scr[OFF_W + ((size_t)e * NDICT + s_cand[k]) * DD];
        float s = 0.f;
        #pragma unroll
        for (int j = 0; j < 16; j++) s += sp[lane + 32 * j] * wr[lane + 32 * j];
        #pragma unroll
        for (int off = 16; off; off >>= 1) s += __shfl_down_sync(0xffffffffu, s, off);
        if (lane == 0) s_exact[k] = s;
    }
    __syncthreads();

    for (int c = tid; c < M; c += 256) {
        unsigned abme = __float_as_uint(s_exact[c]) & 0x7fffffffu;
        unsigned long long me = ((unsigned long long)abme << 32) |
                                (unsigned long long)(0xFFFFFFFFu - (unsigned)s_cand[c]);
        int rank = 0;
        for (int j = 0; j < M; j++) {
            unsigned abj = __float_as_uint(s_exact[j]) & 0x7fffffffu;
            unsigned long long kj = ((unsigned long long)abj << 32) |
                                    (unsigned long long)(0xFFFFFFFFu - (unsigned)s_cand[j]);
            rank += (kj > me);
        }
        if (rank < TOPK) { s_si[rank] = s_cand[c]; s_sv[rank] = s_exact[c]; }
    }
    __syncthreads();

    int which = m >> 10;
    int b = m & 1023;
    int slot = which * 2 + e;
    size_t off = OUT_SP + (size_t)slot * BB * NDICT + (size_t)b * NDICT;
    float4* op = (float4*)(out + off);
    #pragma unroll
    for (int j = 0; j < 16; j++) op[tid + 256 * j] = make_float4(0.f, 0.f, 0.f, 0.f);
    __syncthreads();
    if (tid < TOPK) out[off + s_si[tid]] = s_sv[tid];

    float a0 = 0.f, a1 = 0.f;
    #pragma unroll
    for (int k = 0; k < TOPK; k++) {
        float v = s_sv[k];
        const float* at = atoms + (size_t)s_si[k] * DD;
        a0 += v * at[tid];
        a1 += v * at[tid + 256];
    }
    float* rep = &g_scr[OFF_REP + ((size_t)e * 2 * BB + m) * DD];
    rep[tid]       = a0;
    rep[tid + 256] = a1;
}

// ---------------------------------------------------------------------------
// 6) Heads
// ---------------------------------------------------------------------------
__global__ __launch_bounds__(128) void heads_kernel(const float* __restrict__ cw,
                                                    const float* __restrict__ cb,
                                                    const float* __restrict__ rw,
                                                    const float* __restrict__ rb,
                                                    float* __restrict__ out)
{
    int m = blockIdx.x;
    __shared__ float fused[DD];
    const float* P  = &g_scr[OFF_P   + (size_t)m * DD];
    const float* R0 = &g_scr[OFF_REP + (size_t)m * DD];
    const float* R1 = &g_scr[OFF_REP + (size_t)(2 * BB + m) * DD];
    for (int c = threadIdx.x; c < DD; c += 128)
        fused[c] = 0.2f * P[c] + 0.9f * (R0[c] + R1[c]);
    __syncthreads();

    int lane = threadIdx.x & 31, w = threadIdx.x >> 5;
    int which = m >> 10, b = m & 1023;
    for (int o = w; o < 22; o += 4) {
        const float* wt; float bs; size_t dst;
        if (o < 16) {
            wt = cw + (size_t)o * DD; bs = cb[o];
            dst = (which ? OUT_CN : OUT_CC) + (size_t)b * 16 + o;
        } else {
            int o2 = o - 16;
            wt = rw + (size_t)o2 * DD; bs = rb[o2];
            dst = (which ? OUT_RN : OUT_RC) + (size_t)b * 6 + o2;
        }
        float s = 0.f;
        for (int c = lane; c < DD; c += 32) s += fused[c] * wt[c];
        #pragma unroll
        for (int off = 16; off; off >>= 1) s += __shfl_down_sync(0xffffffffu, s, off);
        if (lane == 0) out[dst] = s + bs;
    }
}

// ---------------------------------------------------------------------------
// Launch
// ---------------------------------------------------------------------------
extern "C" void kernel_launch(void* const* d_in, const int* in_sizes, int n_in,
                              void* d_out, int out_size)
{
    const int*   clean  = (const int*)d_in[0];
    const int*   noisy  = (const int*)d_in[1];
    const float* emb    = (const float*)d_in[2];
    const float* w1     = (const float*)d_in[3];
    const float* b1     = (const float*)d_in[4];
    const float* w2     = (const float*)d_in[5];
    const float* b2     = (const float*)d_in[6];
    const float* atoms  = (const float*)d_in[7];
    const float* router = (const float*)d_in[8];
    const float* cdelta = (const float*)d_in[9];
    const float* rdelta = (const float*)d_in[10];
    const float* chw    = (const float*)d_in[11];
    const float* chb    = (const float*)d_in[12];
    const float* rhw    = (const float*)d_in[13];
    const float* rhb    = (const float*)d_in[14];
    float* out = (float*)d_out;

    float* scr = nullptr;
    cudaGetSymbolAddress((void**)&scr, g_scr);
    __nv_bfloat16* abf = nullptr;
    cudaGetSymbolAddress((void**)&abf, g_A);

    cudaFuncSetAttribute(mma_gemm_kernel,
                         cudaFuncAttributeMaxDynamicSharedMemorySize, MM_SMEM);

    // combined weights (independent, DRAM-bound)
    combine_kernel<<<(NDICT * DD / 4) / 256, 256>>>((const float4*)router,
                                                    (const float4*)cdelta,
                                                    (const float4*)rdelta);
    // pooled token means
    pool_kernel<<<dim3(BB, 2), 128>>>(clean, noisy, emb);

    // MLP: 64x64 tiles, 128 threads, 8x4 microtile, fused epilogues
    dim3 mgrid(DD / 64, (2 * BB) / 64);
    mlp_gemm<<<mgrid, 128>>>(scr + OFF_X, w1, b1, scr + OFF_H, nullptr, 1);
    mlp_gemm<<<mgrid, 128>>>(scr + OFF_H, w2, b2, scr + OFF_P, abf, 0);

    // HMMA coefficient GEMM (both experts), bf16 output
    mma_gemm_kernel<<<dim3(NDICT / 128, (2 * BB) / 128, 2), 256, MM_SMEM>>>();

    // top-k (4096-bin histogram select + exact fp32 fixup) + scatter + rep
    topk_kernel<<<2 * 2 * BB, 256>>>(atoms, out);

    // heads
    heads_kernel<<<2 * BB, 128>>>(chw, chb, rhw, rhb, out);
}

// round 14
// speedup vs baseline: 1.4584x; 1.4584x over previous
#include <cuda_runtime.h>
#include <cuda_bf16.h>
#include <math.h>
#include <stdint.h>

// ---------------------------------------------------------------------------
// Problem constants
// ---------------------------------------------------------------------------
#define BB    1024
#define SS    32
#define DD    512
#define NDICT 16384
#define TOPK  32
#define NSEL  44
#define NBINS 4096        // 12-bit histogram over abs bf16 bits (key >> 3)
#define CANDMAX 512

// ---------------------------------------------------------------------------
// Scratch
// ---------------------------------------------------------------------------
constexpr size_t NX     = 2ULL * BB * DD;          // 2048x512
constexpr size_t OFF_X  = 0;
constexpr size_t OFF_H  = OFF_X + NX;
constexpr size_t OFF_P  = OFF_H + NX;
constexpr size_t OFF_W  = OFF_P + NX;              // combined fp32 W: 2 x 16384 x 512
constexpr size_t NW     = 2ULL * NDICT * DD;
constexpr size_t OFF_REP= OFF_W + NW;              // rep: 2 x 2048 x 512
constexpr size_t NREP   = 2ULL * 2 * BB * DD;
constexpr size_t TOTAL  = OFF_REP + NREP;

__device__ float g_scr[TOTAL];

__device__ __nv_bfloat16 g_A[2048ULL * DD];              // pooled p, bf16
__device__ __nv_bfloat16 g_B[2ULL * NDICT * DD];         // combined W, bf16
__device__ __nv_bfloat16 g_C[2ULL * 2 * BB * NDICT];     // approx coeffs, bf16

// Output layout (floats)
constexpr size_t OUT_CC = 0;
constexpr size_t OUT_RC = 16384;
constexpr size_t OUT_CN = 22528;
constexpr size_t OUT_RN = 38912;
constexpr size_t OUT_SP = 45056;

// ---------------------------------------------------------------------------
// Portable PTX helpers
// ---------------------------------------------------------------------------
__device__ __forceinline__ uint32_t smem_u32(const void* p) {
    uint32_t a;
    asm("{ .reg .u64 t; cvta.to.shared.u64 t, %1; cvt.u32.u64 %0, t; }" : "=r"(a) : "l"(p));
    return a;
}
#define CP_ASYNC16(dst, src) \
    asm volatile("cp.async.cg.shared.global [%0], [%1], 16;" :: "r"(dst), "l"(src))
#define CP_COMMIT()  asm volatile("cp.async.commit_group;" ::: "memory")
#define CP_WAIT_1()  asm volatile("cp.async.wait_group 1;" ::: "memory")
#define CP_WAIT_0()  asm volatile("cp.async.wait_group 0;" ::: "memory")

#define LDMATRIX_X4(r0, r1, r2, r3, addr) \
    asm volatile("ldmatrix.sync.aligned.m8n8.x4.shared.b16 {%0,%1,%2,%3}, [%4];" \
                 : "=r"(r0), "=r"(r1), "=r"(r2), "=r"(r3) : "r"(addr))

#define MMA_BF16(c0, c1, c2, c3, a0, a1, a2, a3, b0, b1) \
    asm volatile("mma.sync.aligned.m16n8k16.row.col.f32.bf16.bf16.f32 " \
                 "{%0,%1,%2,%3}, {%4,%5,%6,%7}, {%8,%9}, {%0,%1,%2,%3};" \
                 : "+f"(c0), "+f"(c1), "+f"(c2), "+f"(c3) \
                 : "r"(a0), "r"(a1), "r"(a2), "r"(a3), "r"(b0), "r"(b1))

#define SWZ128(off) ((off) ^ (((off) >> 3) & 0x70))

__device__ __forceinline__ float silu(float v) { return v / (1.0f + expf(-v)); }

// ---------------------------------------------------------------------------
// 1) Combine router weights -> fp32 W + bf16 B'
// ---------------------------------------------------------------------------
__global__ __launch_bounds__(256) void combine_kernel(const float4* __restrict__ router,
                                                      const float4* __restrict__ cdelta,
                                                      const float4* __restrict__ rdelta)
{
    size_t i = (size_t)blockIdx.x * 256 + threadIdx.x;
    float4 r = router[i];
    float4 c = cdelta[i];
    float4 d = rdelta[i];
    float4 w0 = make_float4(r.x + 0.3f * c.x, r.y + 0.3f * c.y,
                            r.z + 0.3f * c.z, r.w + 0.3f * c.w);
    float4 w1 = make_float4(r.x + 0.3f * d.x, r.y + 0.3f * d.y,
                            r.z + 0.3f * d.z, r.w + 0.3f * d.w);
    ((float4*)&g_scr[OFF_W])[i] = w0;
    ((float4*)&g_scr[OFF_W + (size_t)NDICT * DD])[i] = w1;
    __nv_bfloat162 p0 = __floats2bfloat162_rn(w0.x, w0.y);
    __nv_bfloat162 p1 = __floats2bfloat162_rn(w0.z, w0.w);
    __nv_bfloat162 q0 = __floats2bfloat162_rn(w1.x, w1.y);
    __nv_bfloat162 q1 = __floats2bfloat162_rn(w1.z, w1.w);
    uint2 pk0; pk0.x = *(uint32_t*)&p0; pk0.y = *(uint32_t*)&p1;
    uint2 pk1; pk1.x = *(uint32_t*)&q0; pk1.y = *(uint32_t*)&q1;
    *(uint2*)(g_B + i * 4) = pk0;
    *(uint2*)(g_B + (size_t)NDICT * DD + i * 4) = pk1;
}

// ---------------------------------------------------------------------------
// 2) Pool
// ---------------------------------------------------------------------------
__global__ __launch_bounds__(128) void pool_kernel(const int* __restrict__ clean,
                                                   const int* __restrict__ noisy,
                                                   const float* __restrict__ emb)
{
    int b = blockIdx.x, w = blockIdx.y;
    const int* toks = (w ? noisy : clean) + b * SS;
    __shared__ int st[SS];
    if (threadIdx.x < SS) st[threadIdx.x] = toks[threadIdx.x];
    __syncthreads();
    int c = threadIdx.x;
    float4 acc = make_float4(0.f, 0.f, 0.f, 0.f);
    #pragma unroll
    for (int s = 0; s < SS; s++) {
        const float4 v = *(const float4*)(emb + (size_t)st[s] * DD + c * 4);
        acc.x += v.x; acc.y += v.y; acc.z += v.z; acc.w += v.w;
    }
    const float inv = 1.0f / 32.0f;
    *(float4*)(&g_scr[OFF_X + ((size_t)(w * BB + b)) * DD + c * 4]) =
        make_float4(acc.x * inv, acc.y * inv, acc.z * inv, acc.w * inv);
}

// ---------------------------------------------------------------------------
// 3) MLP GEMM: 64x64 tiles, BK=16, 256 threads, fused bias/act/bf16 epilogue
//    (R11 configuration — best measured)
// ---------------------------------------------------------------------------
__global__ __launch_bounds__(256) void mlp_gemm(const float* __restrict__ A,
                                                const float* __restrict__ Bw,
                                                const float* __restrict__ bias,
                                                float* __restrict__ C,
                                                __nv_bfloat16* __restrict__ Cbf,
                                                int act)
{
    constexpr int BM = 64, BN = 64, BK = 16;
    const int K = DD, N = DD;
    __shared__ float As[BK][BM];
    __shared__ float Bs[BK][BN];
    int tid = threadIdx.x;
    int tx = tid & 15, ty = tid >> 4;
    int row0 = blockIdx.y * BM, col0 = blockIdx.x * BN;
    float acc[4][4] = {};

    int lr = tid >> 2;
    int lc = (tid & 3) * 4;
    const float* Ag = A  + (size_t)(row0 + lr) * K + lc;
    const float* Bg = Bw + (size_t)(col0 + lr) * K + lc;

    float4 an = *(const float4*)Ag;
    float4 bn = *(const float4*)Bg;

    for (int k0 = 0; k0 < K; k0 += BK) {
        As[lc + 0][lr] = an.x; As[lc + 1][lr] = an.y;
        As[lc + 2][lr] = an.z; As[lc + 3][lr] = an.w;
        Bs[lc + 0][lr] = bn.x; Bs[lc + 1][lr] = bn.y;
        Bs[lc + 2][lr] = bn.z; Bs[lc + 3][lr] = bn.w;
        __syncthreads();
        if (k0 + BK < K) {
            an = *(const float4*)(Ag + k0 + BK);
            bn = *(const float4*)(Bg + k0 + BK);
        }
        #pragma unroll
        for (int k = 0; k < BK; k++) {
            float4 a4 = *(const float4*)&As[k][ty * 4];
            float4 b4 = *(const float4*)&Bs[k][tx * 4];
            float ar[4] = {a4.x, a4.y, a4.z, a4.w};
            float br[4] = {b4.x, b4.y, b4.z, b4.w};
            #pragma unroll
            for (int i = 0; i < 4; i++)
                #pragma unroll
                for (int j = 0; j < 4; j++)
                    acc[i][j] += ar[i] * br[j];
        }
        __syncthreads();
    }

    float4 bv = *(const float4*)(bias + col0 + tx * 4);
    #pragma unroll
    for (int i = 0; i < 4; i++) {
        int r = row0 + ty * 4 + i;
        float4 v = make_float4(acc[i][0] + bv.x, acc[i][1] + bv.y,
                               acc[i][2] + bv.z, acc[i][3] + bv.w);
        if (act) { v.x = silu(v.x); v.y = silu(v.y); v.z = silu(v.z); v.w = silu(v.w); }
        *(float4*)(C + (size_t)r * N + col0 + tx * 4) = v;
        if (Cbf) {
            __nv_bfloat162 q0 = __floats2bfloat162_rn(v.x, v.y);
            __nv_bfloat162 q1 = __floats2bfloat162_rn(v.z, v.w);
            uint2 pk; pk.x = *(uint32_t*)&q0; pk.y = *(uint32_t*)&q1;
            *(uint2*)(Cbf + (size_t)r * N + col0 + tx * 4) = pk;
        }
    }
}

// ---------------------------------------------------------------------------
// 4) bf16 mma.sync GEMM (at the sm_103 fallback tensor-issue ceiling)
// ---------------------------------------------------------------------------
constexpr int      NKB      = DD / 64;
constexpr uint32_t TILE_A   = 128 * 128;
constexpr uint32_t TILE_B   = 128 * 128;
constexpr uint32_t STAGE_SZ = TILE_A + TILE_B;
constexpr uint32_t EPI_LD   = 132;
constexpr uint32_t MM_SMEM  = 1024 + 3 * STAGE_SZ;

__device__ __forceinline__ void mm_load(uint32_t sb, const char* Ag, const char* Bg,
                                        int kb, int s, int tid)
{
    uint32_t base = sb + s * STAGE_SZ;
    #pragma unroll
    for (int i = 0; i < 4; i++) {
        int idx = tid + i * 256;
        int r = idx >> 3, c = idx & 7;
        uint32_t off = (uint32_t)(r * 128 + c * 16);
        CP_ASYNC16(base + SWZ128(off), Ag + (size_t)r * 1024 + kb * 128 + c * 16);
    }
    #pragma unroll
    for (int i = 0; i < 4; i++) {
        int idx = tid + i * 256;
        int r = idx >> 3, c = idx & 7;
        uint32_t off = (uint32_t)(r * 128 + c * 16);
        CP_ASYNC16(base + TILE_A + SWZ128(off), Bg + (size_t)r * 1024 + kb * 128 + c * 16);
    }
    CP_COMMIT();
}

__global__ void __launch_bounds__(256, 2) mma_gemm_kernel()
{
    extern __shared__ char smem_raw[];
    uint32_t sb0 = smem_u32(smem_raw);
    uint32_t sb  = (sb0 + 1023u) & ~1023u;
    char* smem = smem_raw + (sb - sb0);

    int tid = threadIdx.x, wid = tid >> 5, lane = tid & 31;
    int nt = blockIdx.x, mt = blockIdx.y, e = blockIdx.z;
    int wm = wid & 1, wn = wid >> 1;

    const char* Ag = (const char*)g_A + (size_t)(mt * 128) * 1024;
    const char* Bg = (const char*)g_B + ((size_t)(e * NDICT + nt * 128)) * 1024;

    float acc[4][4][4];
    #pragma unroll
    for (int i = 0; i < 4; i++)
        #pragma unroll
        for (int j = 0; j < 4; j++)
            #pragma unroll
            for (int v = 0; v < 4; v++) acc[i][j][v] = 0.f;

    uint32_t aOff[4], bOff[2];
    #pragma unroll
    for (int mf = 0; mf < 4; mf++)
        aOff[mf] = (uint32_t)((wm * 64 + mf * 16 + (lane & 15)) * 128 + ((lane >> 4) << 4));
    #pragma unroll
    for (int nf2 = 0; nf2 < 2; nf2++)
        bOff[nf2] = (uint32_t)((wn * 32 + nf2 * 16 + (lane & 7) + ((lane >> 4) << 3)) * 128
                               + (((lane >> 3) & 1) << 4));

    mm_load(sb, Ag, Bg, 0, 0, tid);
    mm_load(sb, Ag, Bg, 1, 1, tid);

    for (int kb = 0; kb < NKB; kb++) {
        int s = kb % 3;
        if (kb + 1 < NKB) { CP_WAIT_1(); } else { CP_WAIT_0(); }
        __syncthreads();
        if (kb + 2 < NKB) mm_load(sb, Ag, Bg, kb + 2, (kb + 2) % 3, tid);

        uint32_t aBase = sb + s * STAGE_SZ;
        uint32_t bBase = aBase + TILE_A;
        #pragma unroll
        for (int ks = 0; ks < 4; ks++) {
            uint32_t a[4][4], b[2][4];
            #pragma unroll
            for (int mf = 0; mf < 4; mf++) {
                uint32_t ad = aBase + SWZ128(aOff[mf] + ks * 32);
                LDMATRIX_X4(a[mf][0], a[mf][1], a[mf][2], a[mf][3], ad);
            }
            #pragma unroll
            for (int nf2 = 0; nf2 < 2; nf2++) {
                uint32_t bd = bBase + SWZ128(bOff[nf2] + ks * 32);
                LDMATRIX_X4(b[nf2][0], b[nf2][1], b[nf2][2], b[nf2][3], bd);
            }
            #pragma unroll
            for (int mf = 0; mf < 4; mf++)
                #pragma unroll
                for (int nf = 0; nf < 4; nf++) {
                    int n2 = nf >> 1, su = (nf & 1) * 2;
                    MMA_BF16(acc[mf][nf][0], acc[mf][nf][1], acc[mf][nf][2], acc[mf][nf][3],
                             a[mf][0], a[mf][1], a[mf][2], a[mf][3],
                             b[n2][su], b[n2][su + 1]);
                }
        }
    }
    __syncthreads();

    float* epi = (float*)smem;
    #pragma unroll
    for (int mf = 0; mf < 4; mf++) {
        int r0 = wm * 64 + mf * 16 + (lane >> 2);
        #pragma unroll
        for (int nf = 0; nf < 4; nf++) {
            int c0 = wn * 32 + nf * 8 + (lane & 3) * 2;
            *(float2*)&epi[(size_t)r0 * EPI_LD + c0] =
                make_float2(acc[mf][nf][0], acc[mf][nf][1]);
            *(float2*)&epi[(size_t)(r0 + 8) * EPI_LD + c0] =
                make_float2(acc[mf][nf][2], acc[mf][nf][3]);
        }
    }
    __syncthreads();

    __nv_bfloat16* C = g_C + ((size_t)e * 2 * BB + mt * 128) * NDICT + nt * 128;
    #pragma unroll
    for (int it = 0; it < 8; it++) {
        int lin = it * 256 + tid;
        int row = lin >> 4;
        int c0  = (lin & 15) * 8;
        const float* sr = epi + (size_t)row * EPI_LD + c0;
        __nv_bfloat162 p0 = __floats2bfloat162_rn(sr[0], sr[1]);
        __nv_bfloat162 p1 = __floats2bfloat162_rn(sr[2], sr[3]);
        __nv_bfloat162 p2 = __floats2bfloat162_rn(sr[4], sr[5]);
        __nv_bfloat162 p3 = __floats2bfloat162_rn(sr[6], sr[7]);
        uint4 pk;
        pk.x = *(uint32_t*)&p0; pk.y = *(uint32_t*)&p1;
        pk.z = *(uint32_t*)&p2; pk.w = *(uint32_t*)&p3;
        *(uint4*)(C + (size_t)row * NDICT + c0) = pk;
    }
}

// ---------------------------------------------------------------------------
// 5) Top-K: 4096-bin histogram threshold -> exact fp32 recompute -> re-rank
// ---------------------------------------------------------------------------
__global__ __launch_bounds__(256) void topk_kernel(const float* __restrict__ atoms,
                                                   float* __restrict__ out)
{
    int g = blockIdx.x;
    int e = g >> 11;
    int m = g & 2047;
    const uint4* row = (const uint4*)(g_C + ((size_t)e * 2 * BB + m) * NDICT);
    int tid = threadIdx.x;
    int lane = tid & 31, wid = tid >> 5;

    __shared__ int   s_hist[NBINS];     // 16KB
    __shared__ int   s_part[256];
    __shared__ int   s_bstar;
    __shared__ int   s_cnt;
    __shared__ int   s_cand[CANDMAX];
    __shared__ float s_exact[CANDMAX];
    __shared__ int   s_si[TOPK];
    __shared__ float s_sv[TOPK];
    __shared__ float sp[DD];

    for (int i = tid; i < NBINS; i += 256) s_hist[i] = 0;
    if (tid == 0) { s_bstar = -1; s_cnt = 0; }
    sp[tid]       = g_scr[OFF_P + (size_t)m * DD + tid];
    sp[tid + 256] = g_scr[OFF_P + (size_t)m * DD + tid + 256];
    __syncthreads();

    uint4 loc[8];
    #pragma unroll
    for (int it = 0; it < 8; it++) loc[it] = row[it * 256 + tid];

    #pragma unroll
    for (int it = 0; it < 8; it++) {
        uint32_t w4[4] = {loc[it].x, loc[it].y, loc[it].z, loc[it].w};
        #pragma unroll
        for (int w = 0; w < 4; w++) {
            unsigned k0 = (w4[w] & 0xFFFFu) & 0x7FFFu;
            unsigned k1 = (w4[w] >> 16) & 0x7FFFu;
            atomicAdd(&s_hist[k0 >> 3], 1);
            atomicAdd(&s_hist[k1 >> 3], 1);
        }
    }
    __syncthreads();

    int base = tid * 16;
    int psum = 0;
    #pragma unroll
    for (int j = 0; j < 16; j++) psum += s_hist[base + j];
    s_part[tid] = psum;
    __syncthreads();
    for (int off = 1; off < 256; off <<= 1) {
        int v = (tid + off < 256) ? s_part[tid + off] : 0;
        __syncthreads();
        s_part[tid] += v;
        __syncthreads();
    }
    int run = (tid + 1 < 256) ? s_part[tid + 1] : 0;
    int best = -1;
    #pragma unroll
    for (int j = 15; j >= 0; j--) {
        run += s_hist[base + j];
        if (best < 0 && run >= NSEL) best = base + j;
    }
    if (best >= 0) atomicMax(&s_bstar, best);
    __syncthreads();

    unsigned Tkey = (unsigned)s_bstar << 3;

    #pragma unroll
    for (int it = 0; it < 8; it++) {
        uint32_t w4[4] = {loc[it].x, loc[it].y, loc[it].z, loc[it].w};
        int ebase = (it * 256 + tid) * 8;
        #pragma unroll
        for (int w = 0; w < 4; w++) {
            unsigned k0 = (w4[w] & 0xFFFFu) & 0x7FFFu;
            unsigned k1 = (w4[w] >> 16) & 0x7FFFu;
            if (k0 >= Tkey) { int p = atomicAdd(&s_cnt, 1); if (p < CANDMAX) s_cand[p] = ebase + w * 2; }
            if (k1 >= Tkey) { int p = atomicAdd(&s_cnt, 1); if (p < CANDMAX) s_cand[p] = ebase + w * 2 + 1; }
        }
    }
    __syncthreads();
    int M = s_cnt < CANDMAX ? s_cnt : CANDMAX;

    for (int k = wid; k < M; k += 8) {
        const float* wr = &g_scr[OFF_W + ((size_t)e * NDICT + s_cand[k]) * DD];
        float s = 0.f;
        #pragma unroll
        for (int j = 0; j < 16; j++) s += sp[lane + 32 * j] * wr[lane + 32 * j];
        #pragma unroll
        for (int off = 16; off; off >>= 1) s += __shfl_down_sync(0xffffffffu, s, off);
        if (lane == 0) s_exact[k] = s;
    }
    __syncthreads();

    for (int c = tid; c < M; c += 256) {
        unsigned abme = __float_as_uint(s_exact[c]) & 0x7fffffffu;
        unsigned long long me = ((unsigned long long)abme << 32) |
                                (unsigned long long)(0xFFFFFFFFu - (unsigned)s_cand[c]);
        int rank = 0;
        for (int j = 0; j < M; j++) {
            unsigned abj = __float_as_uint(s_exact[j]) & 0x7fffffffu;
            unsigned long long kj = ((unsigned long long)abj << 32) |
                                    (unsigned long long)(0xFFFFFFFFu - (unsigned)s_cand[j]);
            rank += (kj > me);
        }
        if (rank < TOPK) { s_si[rank] = s_cand[c]; s_sv[rank] = s_exact[c]; }
    }
    __syncthreads();

    int which = m >> 10;
    int b = m & 1023;
    int slot = which * 2 + e;
    size_t off = OUT_SP + (size_t)slot * BB * NDICT + (size_t)b * NDICT;
    float4* op = (float4*)(out + off);
    #pragma unroll
    for (int j = 0; j < 16; j++) op[tid + 256 * j] = make_float4(0.f, 0.f, 0.f, 0.f);
    __syncthreads();
    if (tid < TOPK) out[off + s_si[tid]] = s_sv[tid];

    float a0 = 0.f, a1 = 0.f;
    #pragma unroll
    for (int k = 0; k < TOPK; k++) {
        float v = s_sv[k];
        const float* at = atoms + (size_t)s_si[k] * DD;
        a0 += v * at[tid];
        a1 += v * at[tid + 256];
    }
    float* rep = &g_scr[OFF_REP + ((size_t)e * 2 * BB + m) * DD];
    rep[tid]       = a0;
    rep[tid + 256] = a1;
}

// ---------------------------------------------------------------------------
// 6) Heads
// ---------------------------------------------------------------------------
__global__ __launch_bounds__(128) void heads_kernel(const float* __restrict__ cw,
                                                    const float* __restrict__ cb,
                                                    const float* __restrict__ rw,
                                                    const float* __restrict__ rb,
                                                    float* __restrict__ out)
{
    int m = blockIdx.x;
    __shared__ float fused[DD];
    const float* P  = &g_scr[OFF_P   + (size_t)m * DD];
    const float* R0 = &g_scr[OFF_REP + (size_t)m * DD];
    const float* R1 = &g_scr[OFF_REP + (size_t)(2 * BB + m) * DD];
    for (int c = threadIdx.x; c < DD; c += 128)
        fused[c] = 0.2f * P[c] + 0.9f * (R0[c] + R1[c]);
    __syncthreads();

    int lane = threadIdx.x & 31, w = threadIdx.x >> 5;
    int which = m >> 10, b = m & 1023;
    for (int o = w; o < 22; o += 4) {
        const float* wt; float bs; size_t dst;
        if (o < 16) {
            wt = cw + (size_t)o * DD; bs = cb[o];
            dst = (which ? OUT_CN : OUT_CC) + (size_t)b * 16 + o;
        } else {
            int o2 = o - 16;
            wt = rw + (size_t)o2 * DD; bs = rb[o2];
            dst = (which ? OUT_RN : OUT_RC) + (size_t)b * 6 + o2;
        }
        float s = 0.f;
        for (int c = lane; c < DD; c += 32) s += fused[c] * wt[c];
        #pragma unroll
        for (int off = 16; off; off >>= 1) s += __shfl_down_sync(0xffffffffu, s, off);
        if (lane == 0) out[dst] = s + bs;
    }
}

// ---------------------------------------------------------------------------
// Launch
// ---------------------------------------------------------------------------
extern "C" void kernel_launch(void* const* d_in, const int* in_sizes, int n_in,
                              void* d_out, int out_size)
{
    const int*   clean  = (const int*)d_in[0];
    const int*   noisy  = (const int*)d_in[1];
    const float* emb    = (const float*)d_in[2];
    const float* w1     = (const float*)d_in[3];
    const float* b1     = (const float*)d_in[4];
    const float* w2     = (const float*)d_in[5];
    const float* b2     = (const float*)d_in[6];
    const float* atoms  = (const float*)d_in[7];
    const float* router = (const float*)d_in[8];
    const float* cdelta = (const float*)d_in[9];
    const float* rdelta = (const float*)d_in[10];
    const float* chw    = (const float*)d_in[11];
    const float* chb    = (const float*)d_in[12];
    const float* rhw    = (const float*)d_in[13];
    const float* rhb    = (const float*)d_in[14];
    float* out = (float*)d_out;

    float* scr = nullptr;
    cudaGetSymbolAddress((void**)&scr, g_scr);
    __nv_bfloat16* abf = nullptr;
    cudaGetSymbolAddress((void**)&abf, g_A);

    cudaFuncSetAttribute(mma_gemm_kernel,
                         cudaFuncAttributeMaxDynamicSharedMemorySize, MM_SMEM);

    // combined weights (independent, DRAM-bound)
    combine_kernel<<<(NDICT * DD / 4) / 256, 256>>>((const float4*)router,
                                                    (const float4*)cdelta,
                                                    (const float4*)rdelta);
    // pooled token means
    pool_kernel<<<dim3(BB, 2), 128>>>(clean, noisy, emb);

    // MLP: 64x64 tiles, full-K, fused bias/act/bf16 epilogues
    dim3 mgrid(DD / 64, (2 * BB) / 64);
    mlp_gemm<<<mgrid, 256>>>(scr + OFF_X, w1, b1, scr + OFF_H, nullptr, 1);
    mlp_gemm<<<mgrid, 256>>>(scr + OFF_H, w2, b2, scr + OFF_P, abf, 0);

    // HMMA coefficient GEMM (both experts), bf16 output
    mma_gemm_kernel<<<dim3(NDICT / 128, (2 * BB) / 128, 2), 256, MM_SMEM>>>();

    // top-k (4096-bin histogram select + exact fp32 fixup) + scatter + rep
    topk_kernel<<<2 * 2 * BB, 256>>>(atoms, out);

    // heads
    heads_kernel<<<2 * BB, 128>>>(chw, chb, rhw, rhb, out);
}

// round 15
// speedup vs baseline: 1.4670x; 1.0059x over previous
#include <cuda_runtime.h>
#include <cuda_bf16.h>
#include <math.h>
#include <stdint.h>

// ---------------------------------------------------------------------------
// Problem constants
// ---------------------------------------------------------------------------
#define BB    1024
#define SS    32
#define DD    512
#define NDICT 16384
#define TOPK  32
#define NSEL  44
#define NBINS 4096        // 12-bit histogram over abs bf16 bits (key >> 3)
#define CANDMAX 512

// ---------------------------------------------------------------------------
// Scratch
// ---------------------------------------------------------------------------
constexpr size_t NX     = 2ULL * BB * DD;          // 2048x512
constexpr size_t OFF_X  = 0;
constexpr size_t OFF_H  = OFF_X + NX;
constexpr size_t OFF_P  = OFF_H + NX;
constexpr size_t OFF_W  = OFF_P + NX;              // combined fp32 W: 2 x 16384 x 512
constexpr size_t NW     = 2ULL * NDICT * DD;
constexpr size_t OFF_REP= OFF_W + NW;              // rep: 2 x 2048 x 512
constexpr size_t NREP   = 2ULL * 2 * BB * DD;
constexpr size_t TOTAL  = OFF_REP + NREP;

__device__ float g_scr[TOTAL];

__device__ __nv_bfloat16 g_A[2048ULL * DD];              // pooled p, bf16
__device__ __nv_bfloat16 g_B[2ULL * NDICT * DD];         // combined W, bf16
__device__ __nv_bfloat16 g_C[2ULL * 2 * BB * NDICT];     // approx coeffs, bf16

// Output layout (floats)
constexpr size_t OUT_CC = 0;
constexpr size_t OUT_RC = 16384;
constexpr size_t OUT_CN = 22528;
constexpr size_t OUT_RN = 38912;
constexpr size_t OUT_SP = 45056;

// ---------------------------------------------------------------------------
// Portable PTX helpers
// ---------------------------------------------------------------------------
__device__ __forceinline__ uint32_t smem_u32(const void* p) {
    uint32_t a;
    asm("{ .reg .u64 t; cvta.to.shared.u64 t, %1; cvt.u32.u64 %0, t; }" : "=r"(a) : "l"(p));
    return a;
}
#define CP_ASYNC16(dst, src) \
    asm volatile("cp.async.cg.shared.global [%0], [%1], 16;" :: "r"(dst), "l"(src))
#define CP_COMMIT()  asm volatile("cp.async.commit_group;" ::: "memory")
#define CP_WAIT_1()  asm volatile("cp.async.wait_group 1;" ::: "memory")
#define CP_WAIT_0()  asm volatile("cp.async.wait_group 0;" ::: "memory")

#define LDMATRIX_X4(r0, r1, r2, r3, addr) \
    asm volatile("ldmatrix.sync.aligned.m8n8.x4.shared.b16 {%0,%1,%2,%3}, [%4];" \
                 : "=r"(r0), "=r"(r1), "=r"(r2), "=r"(r3) : "r"(addr))

#define MMA_BF16(c0, c1, c2, c3, a0, a1, a2, a3, b0, b1) \
    asm volatile("mma.sync.aligned.m16n8k16.row.col.f32.bf16.bf16.f32 " \
                 "{%0,%1,%2,%3}, {%4,%5,%6,%7}, {%8,%9}, {%0,%1,%2,%3};" \
                 : "+f"(c0), "+f"(c1), "+f"(c2), "+f"(c3) \
                 : "r"(a0), "r"(a1), "r"(a2), "r"(a3), "r"(b0), "r"(b1))

#define SWZ128(off) ((off) ^ (((off) >> 3) & 0x70))

__device__ __forceinline__ float silu(float v) { return v / (1.0f + expf(-v)); }

// ---------------------------------------------------------------------------
// 1) Combine router weights -> fp32 W + bf16 B'
// ---------------------------------------------------------------------------
__global__ __launch_bounds__(256) void combine_kernel(const float4* __restrict__ router,
                                                      const float4* __restrict__ cdelta,
                                                      const float4* __restrict__ rdelta)
{
    size_t i = (size_t)blockIdx.x * 256 + threadIdx.x;
    float4 r = router[i];
    float4 c = cdelta[i];
    float4 d = rdelta[i];
    float4 w0 = make_float4(r.x + 0.3f * c.x, r.y + 0.3f * c.y,
                            r.z + 0.3f * c.z, r.w + 0.3f * c.w);
    float4 w1 = make_float4(r.x + 0.3f * d.x, r.y + 0.3f * d.y,
                            r.z + 0.3f * d.z, r.w + 0.3f * d.w);
    ((float4*)&g_scr[OFF_W])[i] = w0;
    ((float4*)&g_scr[OFF_W + (size_t)NDICT * DD])[i] = w1;
    __nv_bfloat162 p0 = __floats2bfloat162_rn(w0.x, w0.y);
    __nv_bfloat162 p1 = __floats2bfloat162_rn(w0.z, w0.w);
    __nv_bfloat162 q0 = __floats2bfloat162_rn(w1.x, w1.y);
    __nv_bfloat162 q1 = __floats2bfloat162_rn(w1.z, w1.w);
    uint2 pk0; pk0.x = *(uint32_t*)&p0; pk0.y = *(uint32_t*)&p1;
    uint2 pk1; pk1.x = *(uint32_t*)&q0; pk1.y = *(uint32_t*)&q1;
    *(uint2*)(g_B + i * 4) = pk0;
    *(uint2*)(g_B + (size_t)NDICT * DD + i * 4) = pk1;
}

// ---------------------------------------------------------------------------
// 2) Pool
// ---------------------------------------------------------------------------
__global__ __launch_bounds__(128) void pool_kernel(const int* __restrict__ clean,
                                                   const int* __restrict__ noisy,
                                                   const float* __restrict__ emb)
{
    int b = blockIdx.x, w = blockIdx.y;
    const int* toks = (w ? noisy : clean) + b * SS;
    __shared__ int st[SS];
    if (threadIdx.x < SS) st[threadIdx.x] = toks[threadIdx.x];
    __syncthreads();
    int c = threadIdx.x;
    float4 acc = make_float4(0.f, 0.f, 0.f, 0.f);
    #pragma unroll
    for (int s = 0; s < SS; s++) {
        const float4 v = *(const float4*)(emb + (size_t)st[s] * DD + c * 4);
        acc.x += v.x; acc.y += v.y; acc.z += v.z; acc.w += v.w;
    }
    const float inv = 1.0f / 32.0f;
    *(float4*)(&g_scr[OFF_X + ((size_t)(w * BB + b)) * DD + c * 4]) =
        make_float4(acc.x * inv, acc.y * inv, acc.z * inv, acc.w * inv);
}

// ---------------------------------------------------------------------------
// 3) MLP GEMM: 64x64 tiles, BK=16, 256 threads, fused bias/act/bf16 epilogue
// ---------------------------------------------------------------------------
__global__ __launch_bounds__(256) void mlp_gemm(const float* __restrict__ A,
                                                const float* __restrict__ Bw,
                                                const float* __restrict__ bias,
                                                float* __restrict__ C,
                                                __nv_bfloat16* __restrict__ Cbf,
                                                int act)
{
    constexpr int BM = 64, BN = 64, BK = 16;
    const int K = DD, N = DD;
    __shared__ float As[BK][BM];
    __shared__ float Bs[BK][BN];
    int tid = threadIdx.x;
    int tx = tid & 15, ty = tid >> 4;
    int row0 = blockIdx.y * BM, col0 = blockIdx.x * BN;
    float acc[4][4] = {};

    int lr = tid >> 2;
    int lc = (tid & 3) * 4;
    const float* Ag = A  + (size_t)(row0 + lr) * K + lc;
    const float* Bg = Bw + (size_t)(col0 + lr) * K + lc;

    float4 an = *(const float4*)Ag;
    float4 bn = *(const float4*)Bg;

    for (int k0 = 0; k0 < K; k0 += BK) {
        As[lc + 0][lr] = an.x; As[lc + 1][lr] = an.y;
        As[lc + 2][lr] = an.z; As[lc + 3][lr] = an.w;
        Bs[lc + 0][lr] = bn.x; Bs[lc + 1][lr] = bn.y;
        Bs[lc + 2][lr] = bn.z; Bs[lc + 3][lr] = bn.w;
        __syncthreads();
        if (k0 + BK < K) {
            an = *(const float4*)(Ag + k0 + BK);
            bn = *(const float4*)(Bg + k0 + BK);
        }
        #pragma unroll
        for (int k = 0; k < BK; k++) {
            float4 a4 = *(const float4*)&As[k][ty * 4];
            float4 b4 = *(const float4*)&Bs[k][tx * 4];
            float ar[4] = {a4.x, a4.y, a4.z, a4.w};
            float br[4] = {b4.x, b4.y, b4.z, b4.w};
            #pragma unroll
            for (int i = 0; i < 4; i++)
                #pragma unroll
                for (int j = 0; j < 4; j++)
                    acc[i][j] += ar[i] * br[j];
        }
        __syncthreads();
    }

    float4 bv = *(const float4*)(bias + col0 + tx * 4);
    #pragma unroll
    for (int i = 0; i < 4; i++) {
        int r = row0 + ty * 4 + i;
        float4 v = make_float4(acc[i][0] + bv.x, acc[i][1] + bv.y,
                               acc[i][2] + bv.z, acc[i][3] + bv.w);
        if (act) { v.x = silu(v.x); v.y = silu(v.y); v.z = silu(v.z); v.w = silu(v.w); }
        *(float4*)(C + (size_t)r * N + col0 + tx * 4) = v;
        if (Cbf) {
            __nv_bfloat162 q0 = __floats2bfloat162_rn(v.x, v.y);
            __nv_bfloat162 q1 = __floats2bfloat162_rn(v.z, v.w);
            uint2 pk; pk.x = *(uint32_t*)&q0; pk.y = *(uint32_t*)&q1;
            *(uint2*)(Cbf + (size_t)r * N + col0 + tx * 4) = pk;
        }
    }
}

// ---------------------------------------------------------------------------
// 4) bf16 mma.sync GEMM (at the sm_103 fallback tensor-issue ceiling)
// ---------------------------------------------------------------------------
constexpr int      NKB      = DD / 64;
constexpr uint32_t TILE_A   = 128 * 128;
constexpr uint32_t TILE_B   = 128 * 128;
constexpr uint32_t STAGE_SZ = TILE_A + TILE_B;
constexpr uint32_t EPI_LD   = 132;
constexpr uint32_t MM_SMEM  = 1024 + 3 * STAGE_SZ;

__device__ __forceinline__ void mm_load(uint32_t sb, const char* Ag, const char* Bg,
                                        int kb, int s, int tid)
{
    uint32_t base = sb + s * STAGE_SZ;
    #pragma unroll
    for (int i = 0; i < 4; i++) {
        int idx = tid + i * 256;
        int r = idx >> 3, c = idx & 7;
        uint32_t off = (uint32_t)(r * 128 + c * 16);
        CP_ASYNC16(base + SWZ128(off), Ag + (size_t)r * 1024 + kb * 128 + c * 16);
    }
    #pragma unroll
    for (int i = 0; i < 4; i++) {
        int idx = tid + i * 256;
        int r = idx >> 3, c = idx & 7;
        uint32_t off = (uint32_t)(r * 128 + c * 16);
        CP_ASYNC16(base + TILE_A + SWZ128(off), Bg + (size_t)r * 1024 + kb * 128 + c * 16);
    }
    CP_COMMIT();
}

__global__ void __launch_bounds__(256, 2) mma_gemm_kernel()
{
    extern __shared__ char smem_raw[];
    uint32_t sb0 = smem_u32(smem_raw);
    uint32_t sb  = (sb0 + 1023u) & ~1023u;
    char* smem = smem_raw + (sb - sb0);

    int tid = threadIdx.x, wid = tid >> 5, lane = tid & 31;
    int nt = blockIdx.x, mt = blockIdx.y, e = blockIdx.z;
    int wm = wid & 1, wn = wid >> 1;

    const char* Ag = (const char*)g_A + (size_t)(mt * 128) * 1024;
    const char* Bg = (const char*)g_B + ((size_t)(e * NDICT + nt * 128)) * 1024;

    float acc[4][4][4];
    #pragma unroll
    for (int i = 0; i < 4; i++)
        #pragma unroll
        for (int j = 0; j < 4; j++)
            #pragma unroll
            for (int v = 0; v < 4; v++) acc[i][j][v] = 0.f;

    uint32_t aOff[4], bOff[2];
    #pragma unroll
    for (int mf = 0; mf < 4; mf++)
        aOff[mf] = (uint32_t)((wm * 64 + mf * 16 + (lane & 15)) * 128 + ((lane >> 4) << 4));
    #pragma unroll
    for (int nf2 = 0; nf2 < 2; nf2++)
        bOff[nf2] = (uint32_t)((wn * 32 + nf2 * 16 + (lane & 7) + ((lane >> 4) << 3)) * 128
                               + (((lane >> 3) & 1) << 4));

    mm_load(sb, Ag, Bg, 0, 0, tid);
    mm_load(sb, Ag, Bg, 1, 1, tid);

    for (int kb = 0; kb < NKB; kb++) {
        int s = kb % 3;
        if (kb + 1 < NKB) { CP_WAIT_1(); } else { CP_WAIT_0(); }
        __syncthreads();
        if (kb + 2 < NKB) mm_load(sb, Ag, Bg, kb + 2, (kb + 2) % 3, tid);

        uint32_t aBase = sb + s * STAGE_SZ;
        uint32_t bBase = aBase + TILE_A;
        #pragma unroll
        for (int ks = 0; ks < 4; ks++) {
            uint32_t a[4][4], b[2][4];
            #pragma unroll
            for (int mf = 0; mf < 4; mf++) {
                uint32_t ad = aBase + SWZ128(aOff[mf] + ks * 32);
                LDMATRIX_X4(a[mf][0], a[mf][1], a[mf][2], a[mf][3], ad);
            }
            #pragma unroll
            for (int nf2 = 0; nf2 < 2; nf2++) {
                uint32_t bd = bBase + SWZ128(bOff[nf2] + ks * 32);
                LDMATRIX_X4(b[nf2][0], b[nf2][1], b[nf2][2], b[nf2][3], bd);
            }
            #pragma unroll
            for (int mf = 0; mf < 4; mf++)
                #pragma unroll
                for (int nf = 0; nf < 4; nf++) {
                    int n2 = nf >> 1, su = (nf & 1) * 2;
                    MMA_BF16(acc[mf][nf][0], acc[mf][nf][1], acc[mf][nf][2], acc[mf][nf][3],
                             a[mf][0], a[mf][1], a[mf][2], a[mf][3],
                             b[n2][su], b[n2][su + 1]);
                }
        }
    }
    __syncthreads();

    float* epi = (float*)smem;
    #pragma unroll
    for (int mf = 0; mf < 4; mf++) {
        int r0 = wm * 64 + mf * 16 + (lane >> 2);
        #pragma unroll
        for (int nf = 0; nf < 4; nf++) {
            int c0 = wn * 32 + nf * 8 + (lane & 3) * 2;
            *(float2*)&epi[(size_t)r0 * EPI_LD + c0] =
                make_float2(acc[mf][nf][0], acc[mf][nf][1]);
            *(float2*)&epi[(size_t)(r0 + 8) * EPI_LD + c0] =
                make_float2(acc[mf][nf][2], acc[mf][nf][3]);
        }
    }
    __syncthreads();

    __nv_bfloat16* C = g_C + ((size_t)e * 2 * BB + mt * 128) * NDICT + nt * 128;
    #pragma unroll
    for (int it = 0; it < 8; it++) {
        int lin = it * 256 + tid;
        int row = lin >> 4;
        int c0  = (lin & 15) * 8;
        const float* sr = epi + (size_t)row * EPI_LD + c0;
        __nv_bfloat162 p0 = __floats2bfloat162_rn(sr[0], sr[1]);
        __nv_bfloat162 p1 = __floats2bfloat162_rn(sr[2], sr[3]);
        __nv_bfloat162 p2 = __floats2bfloat162_rn(sr[4], sr[5]);
        __nv_bfloat162 p3 = __floats2bfloat162_rn(sr[6], sr[7]);
        uint4 pk;
        pk.x = *(uint32_t*)&p0; pk.y = *(uint32_t*)&p1;
        pk.z = *(uint32_t*)&p2; pk.w = *(uint32_t*)&p3;
        *(uint4*)(C + (size_t)row * NDICT + c0) = pk;
    }
}

// ---------------------------------------------------------------------------
// 5) Top-K: 4096-bin histogram threshold -> exact fp32 recompute -> re-rank
// ---------------------------------------------------------------------------
__global__ __launch_bounds__(256) void topk_kernel(const float* __restrict__ atoms,
                                                   float* __restrict__ out)
{
    int g = blockIdx.x;
    int e = g >> 11;
    int m = g & 2047;
    const uint4* row = (const uint4*)(g_C + ((size_t)e * 2 * BB + m) * NDICT);
    int tid = threadIdx.x;
    int lane = tid & 31, wid = tid >> 5;

    __shared__ int   s_hist[NBINS];     // 16KB
    __shared__ int   s_part[256];
    __shared__ int   s_bstar;
    __shared__ int   s_cnt;
    __shared__ int   s_cand[CANDMAX];
    __shared__ float s_exact[CANDMAX];
    __shared__ int   s_si[TOPK];
    __shared__ float s_sv[TOPK];
    __shared__ float sp[DD];

    for (int i = tid; i < NBINS; i += 256) s_hist[i] = 0;
    if (tid == 0) { s_bstar = -1; s_cnt = 0; }
    sp[tid]       = g_scr[OFF_P + (size_t)m * DD + tid];
    sp[tid + 256] = g_scr[OFF_P + (size_t)m * DD + tid + 256];
    __syncthreads();

    uint4 loc[8];
    #pragma unroll
    for (int it = 0; it < 8; it++) loc[it] = row[it * 256 + tid];

    #pragma unroll
    for (int it = 0; it < 8; it++) {
        uint32_t w4[4] = {loc[it].x, loc[it].y, loc[it].z, loc[it].w};
        #pragma unroll
        for (int w = 0; w < 4; w++) {
            unsigned k0 = (w4[w] & 0xFFFFu) & 0x7FFFu;
            unsigned k1 = (w4[w] >> 16) & 0x7FFFu;
            atomicAdd(&s_hist[k0 >> 3], 1);
            atomicAdd(&s_hist[k1 >> 3], 1);
        }
    }
    __syncthreads();

    int base = tid * 16;
    int psum = 0;
    #pragma unroll
    for (int j = 0; j < 16; j++) psum += s_hist[base + j];
    s_part[tid] = psum;
    __syncthreads();
    for (int off = 1; off < 256; off <<= 1) {
        int v = (tid + off < 256) ? s_part[tid + off] : 0;
        __syncthreads();
        s_part[tid] += v;
        __syncthreads();
    }
    int run = (tid + 1 < 256) ? s_part[tid + 1] : 0;
    int best = -1;
    #pragma unroll
    for (int j = 15; j >= 0; j--) {
        run += s_hist[base + j];
        if (best < 0 && run >= NSEL) best = base + j;
    }
    if (best >= 0) atomicMax(&s_bstar, best);
    __syncthreads();

    unsigned Tkey = (unsigned)s_bstar << 3;

    #pragma unroll
    for (int it = 0; it < 8; it++) {
        uint32_t w4[4] = {loc[it].x, loc[it].y, loc[it].z, loc[it].w};
        int ebase = (it * 256 + tid) * 8;
        #pragma unroll
        for (int w = 0; w < 4; w++) {
            unsigned k0 = (w4[w] & 0xFFFFu) & 0x7FFFu;
            unsigned k1 = (w4[w] >> 16) & 0x7FFFu;
            if (k0 >= Tkey) { int p = atomicAdd(&s_cnt, 1); if (p < CANDMAX) s_cand[p] = ebase + w * 2; }
            if (k1 >= Tkey) { int p = atomicAdd(&s_cnt, 1); if (p < CANDMAX) s_cand[p] = ebase + w * 2 + 1; }
        }
    }
    __syncthreads();
    int M = s_cnt < CANDMAX ? s_cnt : CANDMAX;

    for (int k = wid; k < M; k += 8) {
        const float* wr = &g_scr[OFF_W + ((size_t)e * NDICT + s_cand[k]) * DD];
        float s = 0.f;
        #pragma unroll
        for (int j = 0; j < 16; j++) s += sp[lane + 32 * j] * wr[lane + 32 * j];
        #pragma unroll
        for (int off = 16; off; off >>= 1) s += __shfl_down_sync(0xffffffffu, s, off);
        if (lane == 0) s_exact[k] = s;
    }
    __syncthreads();

    for (int c = tid; c < M; c += 256) {
        unsigned abme = __float_as_uint(s_exact[c]) & 0x7fffffffu;
        unsigned long long me = ((unsigned long long)abme << 32) |
                                (unsigned long long)(0xFFFFFFFFu - (unsigned)s_cand[c]);
        int rank = 0;
        for (int j = 0; j < M; j++) {
            unsigned abj = __float_as_uint(s_exact[j]) & 0x7fffffffu;
            unsigned long long kj = ((unsigned long long)abj << 32) |
                                    (unsigned long long)(0xFFFFFFFFu - (unsigned)s_cand[j]);
            rank += (kj > me);
        }
        if (rank < TOPK) { s_si[rank] = s_cand[c]; s_sv[rank] = s_exact[c]; }
    }
    __syncthreads();

    int which = m >> 10;
    int b = m & 1023;
    int slot = which * 2 + e;
    size_t off = OUT_SP + (size_t)slot * BB * NDICT + (size_t)b * NDICT;
    float4* op = (float4*)(out + off);
    #pragma unroll
    for (int j = 0; j < 16; j++) op[tid + 256 * j] = make_float4(0.f, 0.f, 0.f, 0.f);
    __syncthreads();
    if (tid < TOPK) out[off + s_si[tid]] = s_sv[tid];

    float a0 = 0.f, a1 = 0.f;
    #pragma unroll
    for (int k = 0; k < TOPK; k++) {
        float v = s_sv[k];
        const float* at = atoms + (size_t)s_si[k] * DD;
        a0 += v * at[tid];
        a1 += v * at[tid + 256];
    }
    float* rep = &g_scr[OFF_REP + ((size_t)e * 2 * BB + m) * DD];
    rep[tid]       = a0;
    rep[tid + 256] = a1;
}

// ---------------------------------------------------------------------------
// 6) Heads
// ---------------------------------------------------------------------------
__global__ __launch_bounds__(128) void heads_kernel(const float* __restrict__ cw,
                                                    const float* __restrict__ cb,
                                                    const float* __restrict__ rw,
                                                    const float* __restrict__ rb,
                                                    float* __restrict__ out)
{
    int m = blockIdx.x;
    __shared__ float fused[DD];
    const float* P  = &g_scr[OFF_P   + (size_t)m * DD];
    const float* R0 = &g_scr[OFF_REP + (size_t)m * DD];
    const float* R1 = &g_scr[OFF_REP + (size_t)(2 * BB + m) * DD];
    for (int c = threadIdx.x; c < DD; c += 128)
        fused[c] = 0.2f * P[c] + 0.9f * (R0[c] + R1[c]);
    __syncthreads();

    int lane = threadIdx.x & 31, w = threadIdx.x >> 5;
    int which = m >> 10, b = m & 1023;
    for (int o = w; o < 22; o += 4) {
        const float* wt; float bs; size_t dst;
        if (o < 16) {
            wt = cw + (size_t)o * DD; bs = cb[o];
            dst = (which ? OUT_CN : OUT_CC) + (size_t)b * 16 + o;
        } else {
            int o2 = o - 16;
            wt = rw + (size_t)o2 * DD; bs = rb[o2];
            dst = (which ? OUT_RN : OUT_RC) + (size_t)b * 6 + o2;
        }
        float s = 0.f;
        for (int c = lane; c < DD; c += 32) s += fused[c] * wt[c];
        #pragma unroll
        for (int off = 16; off; off >>= 1) s += __shfl_down_sync(0xffffffffu, s, off);
        if (lane == 0) out[dst] = s + bs;
    }
}

// ---------------------------------------------------------------------------
// Launch: combine forked onto a side stream (graph captures the parallelism)
// ---------------------------------------------------------------------------
extern "C" void kernel_launch(void* const* d_in, const int* in_sizes, int n_in,
                              void* d_out, int out_size)
{
    const int*   clean  = (const int*)d_in[0];
    const int*   noisy  = (const int*)d_in[1];
    const float* emb    = (const float*)d_in[2];
    const float* w1     = (const float*)d_in[3];
    const float* b1     = (const float*)d_in[4];
    const float* w2     = (const float*)d_in[5];
    const float* b2     = (const float*)d_in[6];
    const float* atoms  = (const float*)d_in[7];
    const float* router = (const float*)d_in[8];
    const float* cdelta = (const float*)d_in[9];
    const float* rdelta = (const float*)d_in[10];
    const float* chw    = (const float*)d_in[11];
    const float* chb    = (const float*)d_in[12];
    const float* rhw    = (const float*)d_in[13];
    const float* rhb    = (const float*)d_in[14];
    float* out = (float*)d_out;

    float* scr = nullptr;
    cudaGetSymbolAddress((void**)&scr, g_scr);
    __nv_bfloat16* abf = nullptr;
    cudaGetSymbolAddress((void**)&abf, g_A);

    cudaFuncSetAttribute(mma_gemm_kernel,
                         cudaFuncAttributeMaxDynamicSharedMemorySize, MM_SMEM);

    // One-time resource init (first call is the eager correctness run, before
    // graph capture; per-call work is identical and deterministic).
    static cudaStream_t s2 = nullptr;
    static cudaEvent_t  ev_fork = nullptr, ev_join = nullptr;
    if (s2 == nullptr) {
        cudaStreamCreateWithFlags(&s2, cudaStreamNonBlocking);
        cudaEventCreateWithFlags(&ev_fork, cudaEventDisableTiming);
        cudaEventCreateWithFlags(&ev_join, cudaEventDisableTiming);
    }

    // Fork: combine (DRAM-bound, independent) runs concurrently with the
    // compute-bound pool -> mlp1 -> mlp2 chain.
    cudaEventRecord(ev_fork, 0);
    cudaStreamWaitEvent(s2, ev_fork, 0);
    combine_kernel<<<(NDICT * DD / 4) / 256, 256, 0, s2>>>((const float4*)router,
                                                           (const float4*)cdelta,
                                                           (const float4*)rdelta);
    cudaEventRecord(ev_join, s2);

    // Main chain
    pool_kernel<<<dim3(BB, 2), 128>>>(clean, noisy, emb);
    dim3 mgrid(DD / 64, (2 * BB) / 64);
    mlp_gemm<<<mgrid, 256>>>(scr + OFF_X, w1, b1, scr + OFF_H, nullptr, 1);
    mlp_gemm<<<mgrid, 256>>>(scr + OFF_H, w2, b2, scr + OFF_P, abf, 0);

    // Join: mma_gemm needs g_B (combine) and g_A (mlp2)
    cudaStreamWaitEvent(0, ev_join, 0);

    mma_gemm_kernel<<<dim3(NDICT / 128, (2 * BB) / 128, 2), 256, MM_SMEM>>>();
    topk_kernel<<<2 * 2 * BB, 256>>>(atoms, out);
    heads_kernel<<<2 * BB, 128>>>(chw, chb, rhw, rhb, out);
}